// round 13
// baseline (speedup 1.0000x reference)
#include <cuda_runtime.h>
#include <cuda_fp16.h>
#include <stdint.h>

#define FXD 64
#define HD 256
#define NTHR 256
#define NW   8

// ---- Precomputed u[b]@W1[128:192] + b1 : [512,128] half2 ----
__device__ __align__(16) __half2 g_ubbh[512 * 128];

__global__ void ubb_kernel(const float* __restrict__ u,
                           const float* __restrict__ W1,
                           const float* __restrict__ b1) {
    __shared__ float us[FXD];
    __shared__ float accs[HD];
    int b = blockIdx.x, c = threadIdx.x;
    if (c < FXD) us[c] = u[b * FXD + c];
    __syncthreads();
    float acc = b1[c];
#pragma unroll 16
    for (int k = 0; k < FXD; ++k)
        acc = fmaf(us[k], W1[(2 * FXD + k) * HD + c], acc);
    accs[c] = acc;
    __syncthreads();
    if (c < 128)
        g_ubbh[b * 128 + c] = __floats2half2_rn(accs[2 * c], accs[2 * c + 1]);
}

__device__ __forceinline__ uint32_t packf16(float a, float b) {
    __half2 h = __floats2half2_rn(a, b);
    return *reinterpret_cast<uint32_t*>(&h);
}

__device__ __forceinline__ void mma16816(float* c, const uint32_t* a,
                                         uint32_t b0, uint32_t b1) {
    asm volatile(
        "mma.sync.aligned.m16n8k16.row.col.f32.f16.f16.f32 "
        "{%0,%1,%2,%3}, {%4,%5,%6,%7}, {%8,%9}, {%0,%1,%2,%3};"
        : "+f"(c[0]), "+f"(c[1]), "+f"(c[2]), "+f"(c[3])
        : "r"(a[0]), "r"(a[1]), "r"(a[2]), "r"(a[3]), "r"(b0), "r"(b1));
}

// SMEM (uint4 units):
//   w1s 4096 (64KB), w2s 2048 (32KB), outbuf 8 warps x 32x68 floats (68KB), b2 64 floats
#define W2_OFF   4096
#define OUT_OFF  6144
#define B2_OFF   (6144 + 4352)
#define SMEM_SZ  ((6144 + 4352 + 16) * 16)
#define OSTRIDE  68

__global__ __launch_bounds__(NTHR, 1)
void edge_mlp_hmma(const float* __restrict__ src,
                   const float* __restrict__ dst,
                   const int* __restrict__ batch,
                   const float* __restrict__ W1,
                   const float* __restrict__ W2,
                   const float* __restrict__ b2,
                   float* __restrict__ out, int E, int B)
{
    extern __shared__ uint4 smem4[];
    uint4* w1s = smem4;
    uint4* w2s = smem4 + W2_OFF;
    float* b2s = (float*)(smem4 + B2_OFF);

    const int tid  = threadIdx.x;
    const int wid  = tid >> 5;
    const int lane = tid & 31;
    const int gg   = lane >> 2;   // group row
    const int tig  = lane & 3;    // thread in group

    float* outs = (float*)(smem4 + OUT_OFF) + wid * (32 * OSTRIDE);

    // ---- stage W1 fp16 B-fragments ----
    for (int i = tid; i < 8 * 16 * 32 * 4; i += NTHR) {
        int c = i & 3, t = (i >> 2) & 31, ntp = (i >> 7) & 15, s = i >> 11;
        int h = c >> 1, p = c & 1;
        int n  = (2 * ntp + h) * 8 + (t >> 2);
        int k0 = s * 16 + 2 * (t & 3) + p * 8;
        ((uint32_t*)&w1s[(s * 16 + ntp) * 32 + t])[c] =
            packf16(W1[k0 * HD + n], W1[(k0 + 1) * HD + n]);
    }
    // ---- stage W2 ----
    for (int i = tid; i < 16 * 4 * 32 * 4; i += NTHR) {
        int c = i & 3, t = (i >> 2) & 31, ntp = (i >> 7) & 3, s = i >> 9;
        int h = c >> 1, p = c & 1;
        int n  = (2 * ntp + h) * 8 + (t >> 2);
        int k0 = s * 16 + 2 * (t & 3) + p * 8;
        ((uint32_t*)&w2s[(s * 4 + ntp) * 32 + t])[c] =
            packf16(W2[k0 * 64 + n], W2[(k0 + 1) * 64 + n]);
    }
    if (tid < 64) b2s[tid] = b2[tid];
    __syncthreads();

    // ---- warp-autonomous loop over 32-edge groups ----
    const int ngroups = (E + 31) >> 5;
    const int gw0     = blockIdx.x * NW + wid;
    const int gstride = gridDim.x * NW;

    for (int g = gw0; g < ngroups; g += gstride) {
        const int ebase = g * 32 + gg;
        uint32_t eo[4];   // x row offsets (floats)
        uint32_t uo[4];   // ubbh row offsets (half2)
#pragma unroll
        for (int j = 0; j < 4; ++j) {
            int e = ebase + 8 * j;
            int ec = e < E ? e : (E - 1);
            eo[j] = (uint32_t)ec * 64u;
            int bi = batch[ec];
            bi = min(max(bi, 0), B - 1);
            uo[j] = (uint32_t)bi * 128u;
        }

        // ---- load A1 fragments: Ah[s][0..3] = mtile0, [4..7] = mtile1 ----
        uint32_t Ah[8][8];
#pragma unroll
        for (int s = 0; s < 8; ++s) {
            const float* xp = (s < 4) ? dst : src;
            const int k = (s & 3) * 16 + 2 * tig;
#pragma unroll
            for (int m = 0; m < 2; ++m) {
                float2 pa0 = *(const float2*)(xp + eo[2 * m]     + k);
                float2 pa1 = *(const float2*)(xp + eo[2 * m]     + k + 8);
                float2 pb0 = *(const float2*)(xp + eo[2 * m + 1] + k);
                float2 pb1 = *(const float2*)(xp + eo[2 * m + 1] + k + 8);
                Ah[s][4 * m + 0] = packf16(pa0.x, pa0.y);
                Ah[s][4 * m + 1] = packf16(pb0.x, pb0.y);
                Ah[s][4 * m + 2] = packf16(pa1.x, pa1.y);
                Ah[s][4 * m + 3] = packf16(pb1.x, pb1.y);
            }
        }

        // C2[(nt2*2 + m)*4 + r] : 32 rows x 64 cols
        float C2[64];
#pragma unroll
        for (int i = 0; i < 64; ++i) C2[i] = 0.f;

        // ---- 8 chunk-PAIRS of 2x16 hidden cols; 8 independent C1 chains ----
#pragma unroll
        for (int cp = 0; cp < 8; ++cp) {
            const int cA = 2 * cp, cB = 2 * cp + 1;

            // (1) prefetch ubb half2 operands for both chunks
            __half2 U[2][2][2][2];   // [cc][m][h][row-pair]
#pragma unroll
            for (int cc = 0; cc < 2; ++cc)
#pragma unroll
                for (int m = 0; m < 2; ++m)
#pragma unroll
                    for (int h = 0; h < 2; ++h) {
                        const int ci = (2 * cp + cc) * 8 + h * 4 + tig;
                        U[cc][m][h][0] = g_ubbh[uo[2 * m]     + ci];
                        U[cc][m][h][1] = g_ubbh[uo[2 * m + 1] + ci];
                    }

            // (2) paired GEMM1: C1[((cc*2 + j)*2 + m)*4 + r], 8 indep chains
            float C1[32];
#pragma unroll
            for (int i = 0; i < 32; ++i) C1[i] = 0.f;
            uint4 wvA = w1s[(0 * 16 + cA) * 32 + lane];
            uint4 wvB = w1s[(0 * 16 + cB) * 32 + lane];
#pragma unroll
            for (int s = 0; s < 8; ++s) {
                uint4 wvAn, wvBn;
                if (s < 7) {
                    wvAn = w1s[((s + 1) * 16 + cA) * 32 + lane];
                    wvBn = w1s[((s + 1) * 16 + cB) * 32 + lane];
                }
#pragma unroll
                for (int m = 0; m < 2; ++m) {
                    mma16816(C1 + ((0 * 2 + 0) * 2 + m) * 4, Ah[s] + 4 * m, wvA.x, wvA.y);
                    mma16816(C1 + ((1 * 2 + 0) * 2 + m) * 4, Ah[s] + 4 * m, wvB.x, wvB.y);
                    mma16816(C1 + ((0 * 2 + 1) * 2 + m) * 4, Ah[s] + 4 * m, wvA.z, wvA.w);
                    mma16816(C1 + ((1 * 2 + 1) * 2 + m) * 4, Ah[s] + 4 * m, wvB.z, wvB.w);
                }
                wvA = wvAn; wvB = wvBn;
            }

            // (3) per chunk: epilogue + GEMM2
#pragma unroll
            for (int cc = 0; cc < 2; ++cc) {
                const int c1 = 2 * cp + cc;
                uint4 wv2[4];
#pragma unroll
                for (int ntp = 0; ntp < 4; ++ntp)
                    wv2[ntp] = w2s[(c1 * 4 + ntp) * 32 + lane];

                uint32_t A2[2][4];
                const __half2 hz = __floats2half2_rn(0.f, 0.f);
#pragma unroll
                for (int m = 0; m < 2; ++m) {
#pragma unroll
                    for (int h = 0; h < 2; ++h) {
                        const float* cp2 = C1 + ((cc * 2 + h) * 2 + m) * 4;
                        __half2 t0 = __hmax2(__hadd2(__floats2half2_rn(cp2[0], cp2[1]), U[cc][m][h][0]), hz);
                        __half2 t1 = __hmax2(__hadd2(__floats2half2_rn(cp2[2], cp2[3]), U[cc][m][h][1]), hz);
                        A2[m][2 * h + 0] = *reinterpret_cast<uint32_t*>(&t0);
                        A2[m][2 * h + 1] = *reinterpret_cast<uint32_t*>(&t1);
                    }
                }
#pragma unroll
                for (int ntp = 0; ntp < 4; ++ntp) {
#pragma unroll
                    for (int m = 0; m < 2; ++m) {
                        mma16816(C2 + ((2 * ntp + 0) * 2 + m) * 4, A2[m], wv2[ntp].x, wv2[ntp].y);
                        mma16816(C2 + ((2 * ntp + 1) * 2 + m) * 4, A2[m], wv2[ntp].z, wv2[ntp].w);
                    }
                }
            }
        }

        // ---- store: stage C2 in smem, then coalesced STG.128 ----
        if (g * 32 + 32 <= E) {
            __syncwarp();
#pragma unroll
            for (int nt2 = 0; nt2 < 8; ++nt2) {
                const int col = nt2 * 8 + 2 * tig;
#pragma unroll
                for (int m = 0; m < 2; ++m) {
                    const float* cp2 = C2 + (nt2 * 2 + m) * 4;
                    const int r0 = 16 * m + gg;
                    *(float2*)(outs + r0 * OSTRIDE + col)       = make_float2(cp2[0], cp2[1]);
                    *(float2*)(outs + (r0 + 8) * OSTRIDE + col) = make_float2(cp2[2], cp2[3]);
                }
            }
            __syncwarp();
            float* og = out + (uint32_t)g * 2048u;
            const float4* b2v = (const float4*)b2s;
#pragma unroll
            for (int t = 0; t < 16; ++t) {
                int idx = t * 32 + lane;
                int r = idx >> 4, c4 = idx & 15;
                float4 v = *(const float4*)(outs + r * OSTRIDE + c4 * 4);
                float4 bb = b2v[c4];
                v.x += bb.x; v.y += bb.y; v.z += bb.z; v.w += bb.w;
                *(float4*)(og + idx * 4) = v;
            }
            __syncwarp();
        } else {
            // tail fallback (unused when E % 32 == 0)
#pragma unroll
            for (int nt2 = 0; nt2 < 8; ++nt2) {
                const int col = nt2 * 8 + 2 * tig;
                const float bx = b2s[col], by = b2s[col + 1];
#pragma unroll
                for (int m = 0; m < 2; ++m) {
                    const float* cp2 = C2 + (nt2 * 2 + m) * 4;
                    if (ebase + 16 * m < E) {
                        float2 o; o.x = cp2[0] + bx; o.y = cp2[1] + by;
                        *(float2*)(out + eo[2 * m] + col) = o;
                    }
                    if (ebase + 16 * m + 8 < E) {
                        float2 o; o.x = cp2[2] + bx; o.y = cp2[3] + by;
                        *(float2*)(out + eo[2 * m + 1] + col) = o;
                    }
                }
            }
        }
    }
}

extern "C" void kernel_launch(void* const* d_in, const int* in_sizes, int n_in,
                              void* d_out, int out_size) {
    const float* src   = (const float*)d_in[0];
    const float* dest  = (const float*)d_in[1];
    /* d_in[2] = edge_attr, unused by the reference */
    const float* u     = (const float*)d_in[3];
    const int*   batch = (const int*)d_in[4];
    const float* W1    = (const float*)d_in[5];
    const float* b1    = (const float*)d_in[6];
    const float* W2    = (const float*)d_in[7];
    const float* b2    = (const float*)d_in[8];
    float* out = (float*)d_out;

    int E = in_sizes[4];
    int B = in_sizes[3] / FXD;

    ubb_kernel<<<B, 256>>>(u, W1, b1);

    int nsm = 148;
    cudaDeviceGetAttribute(&nsm, cudaDevAttrMultiProcessorCount, 0);
    long ngroups = ((long)E + 31) >> 5;
    long maxcta  = (ngroups + NW - 1) / NW;
    int grid = (int)(maxcta < (long)nsm ? maxcta : (long)nsm);

    cudaFuncSetAttribute(edge_mlp_hmma,
                         cudaFuncAttributeMaxDynamicSharedMemorySize, SMEM_SZ);
    edge_mlp_hmma<<<grid, NTHR, SMEM_SZ>>>(src, dest, batch, W1, W2, b2, out, E, B);
}

// round 14
// speedup vs baseline: 1.0409x; 1.0409x over previous
#include <cuda_runtime.h>
#include <cuda_fp16.h>
#include <stdint.h>

#define FXD 64
#define HD 256
#define NTHR 256
#define NW   8

// ---- Precomputed u[b]@W1[128:192] + b1 : [512,128] half2 ----
__device__ __align__(16) __half2 g_ubbh[512 * 128];

__global__ void ubb_kernel(const float* __restrict__ u,
                           const float* __restrict__ W1,
                           const float* __restrict__ b1) {
    __shared__ float us[FXD];
    __shared__ float accs[HD];
    int b = blockIdx.x, c = threadIdx.x;
    if (c < FXD) us[c] = u[b * FXD + c];
    __syncthreads();
    float acc = b1[c];
#pragma unroll 16
    for (int k = 0; k < FXD; ++k)
        acc = fmaf(us[k], W1[(2 * FXD + k) * HD + c], acc);
    accs[c] = acc;
    __syncthreads();
    if (c < 128)
        g_ubbh[b * 128 + c] = __floats2half2_rn(accs[2 * c], accs[2 * c + 1]);
}

__device__ __forceinline__ uint32_t packf16(float a, float b) {
    __half2 h = __floats2half2_rn(a, b);
    return *reinterpret_cast<uint32_t*>(&h);
}

__device__ __forceinline__ void mma16816(float* c, const uint32_t* a,
                                         uint32_t b0, uint32_t b1) {
    asm volatile(
        "mma.sync.aligned.m16n8k16.row.col.f32.f16.f16.f32 "
        "{%0,%1,%2,%3}, {%4,%5,%6,%7}, {%8,%9}, {%0,%1,%2,%3};"
        : "+f"(c[0]), "+f"(c[1]), "+f"(c[2]), "+f"(c[3])
        : "r"(a[0]), "r"(a[1]), "r"(a[2]), "r"(a[3]), "r"(b0), "r"(b1));
}

// SMEM (uint4 units):
//   w1s 4096 (64KB), w2s 2048 (32KB), outbuf 8 warps x 32x68 floats (68KB), b2 64 floats
#define W2_OFF   4096
#define OUT_OFF  6144
#define B2_OFF   (6144 + 4352)
#define SMEM_SZ  ((6144 + 4352 + 16) * 16)
#define OSTRIDE  68

__global__ __launch_bounds__(NTHR, 1)
void edge_mlp_hmma(const float* __restrict__ src,
                   const float* __restrict__ dst,
                   const int* __restrict__ batch,
                   const float* __restrict__ W1,
                   const float* __restrict__ W2,
                   const float* __restrict__ b2,
                   float* __restrict__ out, int E, int B)
{
    extern __shared__ uint4 smem4[];
    uint4* w1s = smem4;
    uint4* w2s = smem4 + W2_OFF;
    float* b2s = (float*)(smem4 + B2_OFF);

    const int tid  = threadIdx.x;
    const int wid  = tid >> 5;
    const int lane = tid & 31;
    const int gg   = lane >> 2;   // group row
    const int tig  = lane & 3;    // thread in group

    float* outs = (float*)(smem4 + OUT_OFF) + wid * (32 * OSTRIDE);

    // ---- stage W1 fp16 B-fragments ----
    for (int i = tid; i < 8 * 16 * 32 * 4; i += NTHR) {
        int c = i & 3, t = (i >> 2) & 31, ntp = (i >> 7) & 15, s = i >> 11;
        int h = c >> 1, p = c & 1;
        int n  = (2 * ntp + h) * 8 + (t >> 2);
        int k0 = s * 16 + 2 * (t & 3) + p * 8;
        ((uint32_t*)&w1s[(s * 16 + ntp) * 32 + t])[c] =
            packf16(W1[k0 * HD + n], W1[(k0 + 1) * HD + n]);
    }
    // ---- stage W2 ----
    for (int i = tid; i < 16 * 4 * 32 * 4; i += NTHR) {
        int c = i & 3, t = (i >> 2) & 31, ntp = (i >> 7) & 3, s = i >> 9;
        int h = c >> 1, p = c & 1;
        int n  = (2 * ntp + h) * 8 + (t >> 2);
        int k0 = s * 16 + 2 * (t & 3) + p * 8;
        ((uint32_t*)&w2s[(s * 4 + ntp) * 32 + t])[c] =
            packf16(W2[k0 * 64 + n], W2[(k0 + 1) * 64 + n]);
    }
    if (tid < 64) b2s[tid] = b2[tid];
    __syncthreads();

    // ---- phase-offset: second warp on each SMSP starts ~half a chunk later ----
    if (wid >= 4) {
        unsigned long long t0 = clock64();
        while (clock64() - t0 < 700ull) { }
    }

    // ---- warp-autonomous loop over 32-edge groups ----
    const int ngroups = (E + 31) >> 5;
    const int gw0     = blockIdx.x * NW + wid;
    const int gstride = gridDim.x * NW;

    for (int g = gw0; g < ngroups; g += gstride) {
        const int ebase = g * 32 + gg;
        uint32_t eo[4];   // x row offsets (floats)
        uint32_t uo[4];   // ubbh row offsets (half2)
#pragma unroll
        for (int j = 0; j < 4; ++j) {
            int e = ebase + 8 * j;
            int ec = e < E ? e : (E - 1);
            eo[j] = (uint32_t)ec * 64u;
            int bi = batch[ec];
            bi = min(max(bi, 0), B - 1);
            uo[j] = (uint32_t)bi * 128u;
        }

        // ---- load A1 fragments: Ah[s][0..3] = mtile0, [4..7] = mtile1 ----
        uint32_t Ah[8][8];
#pragma unroll
        for (int s = 0; s < 8; ++s) {
            const float* xp = (s < 4) ? dst : src;
            const int k = (s & 3) * 16 + 2 * tig;
#pragma unroll
            for (int m = 0; m < 2; ++m) {
                float2 pa0 = *(const float2*)(xp + eo[2 * m]     + k);
                float2 pa1 = *(const float2*)(xp + eo[2 * m]     + k + 8);
                float2 pb0 = *(const float2*)(xp + eo[2 * m + 1] + k);
                float2 pb1 = *(const float2*)(xp + eo[2 * m + 1] + k + 8);
                Ah[s][4 * m + 0] = packf16(pa0.x, pa0.y);
                Ah[s][4 * m + 1] = packf16(pb0.x, pb0.y);
                Ah[s][4 * m + 2] = packf16(pa1.x, pa1.y);
                Ah[s][4 * m + 3] = packf16(pb1.x, pb1.y);
            }
        }

        // C2[(nt2*2 + m)*4 + r] : 32 rows x 64 cols
        float C2[64];
#pragma unroll
        for (int i = 0; i < 64; ++i) C2[i] = 0.f;

        // ---- 16 chunks of 16 hidden cols (chunk == one W2 k-step) ----
#pragma unroll
        for (int c1 = 0; c1 < 16; ++c1) {
            // (1) prefetch ubb half2 operands
            __half2 U[2][2][2];
#pragma unroll
            for (int m = 0; m < 2; ++m)
#pragma unroll
                for (int h = 0; h < 2; ++h) {
                    const int ci = c1 * 8 + h * 4 + tig;
                    U[m][h][0] = g_ubbh[uo[2 * m]     + ci];
                    U[m][h][1] = g_ubbh[uo[2 * m + 1] + ci];
                }

            // (2) GEMM1 chunk with double-buffered weight fragments
            float C1[16];
#pragma unroll
            for (int i = 0; i < 16; ++i) C1[i] = 0.f;
            uint4 wv = w1s[(0 * 16 + c1) * 32 + lane];
#pragma unroll
            for (int s = 0; s < 8; ++s) {
                uint4 wvn;
                if (s < 7) wvn = w1s[((s + 1) * 16 + c1) * 32 + lane];
#pragma unroll
                for (int m = 0; m < 2; ++m) {
                    mma16816(C1 + (0 * 2 + m) * 4, Ah[s] + 4 * m, wv.x, wv.y);
                    mma16816(C1 + (1 * 2 + m) * 4, Ah[s] + 4 * m, wv.z, wv.w);
                }
                wv = wvn;
            }

            // (3) preload GEMM2 fragments
            uint4 wv2[4];
#pragma unroll
            for (int ntp = 0; ntp < 4; ++ntp)
                wv2[ntp] = w2s[(c1 * 4 + ntp) * 32 + lane];

            // (4) epilogue in half2: A2 = relu(f16(C1) + ubbh)
            uint32_t A2[2][4];
            const __half2 hz = __floats2half2_rn(0.f, 0.f);
#pragma unroll
            for (int m = 0; m < 2; ++m) {
#pragma unroll
                for (int h = 0; h < 2; ++h) {
                    const float* cp = C1 + (h * 2 + m) * 4;
                    __half2 t0 = __hmax2(__hadd2(__floats2half2_rn(cp[0], cp[1]), U[m][h][0]), hz);
                    __half2 t1 = __hmax2(__hadd2(__floats2half2_rn(cp[2], cp[3]), U[m][h][1]), hz);
                    A2[m][2 * h + 0] = *reinterpret_cast<uint32_t*>(&t0);
                    A2[m][2 * h + 1] = *reinterpret_cast<uint32_t*>(&t1);
                }
            }

            // (5) GEMM2 partial: k-step c1
#pragma unroll
            for (int ntp = 0; ntp < 4; ++ntp) {
#pragma unroll
                for (int m = 0; m < 2; ++m) {
                    mma16816(C2 + ((2 * ntp + 0) * 2 + m) * 4, A2[m], wv2[ntp].x, wv2[ntp].y);
                    mma16816(C2 + ((2 * ntp + 1) * 2 + m) * 4, A2[m], wv2[ntp].z, wv2[ntp].w);
                }
            }
        }

        // ---- store: stage C2 in smem, then coalesced STG.128 ----
        if (g * 32 + 32 <= E) {
            __syncwarp();
#pragma unroll
            for (int nt2 = 0; nt2 < 8; ++nt2) {
                const int col = nt2 * 8 + 2 * tig;
#pragma unroll
                for (int m = 0; m < 2; ++m) {
                    const float* cp = C2 + (nt2 * 2 + m) * 4;
                    const int r0 = 16 * m + gg;
                    *(float2*)(outs + r0 * OSTRIDE + col)       = make_float2(cp[0], cp[1]);
                    *(float2*)(outs + (r0 + 8) * OSTRIDE + col) = make_float2(cp[2], cp[3]);
                }
            }
            __syncwarp();
            float* og = out + (uint32_t)g * 2048u;
            const float4* b2v = (const float4*)b2s;
#pragma unroll
            for (int t = 0; t < 16; ++t) {
                int idx = t * 32 + lane;
                int r = idx >> 4, c4 = idx & 15;
                float4 v = *(const float4*)(outs + r * OSTRIDE + c4 * 4);
                float4 bb = b2v[c4];
                v.x += bb.x; v.y += bb.y; v.z += bb.z; v.w += bb.w;
                *(float4*)(og + idx * 4) = v;
            }
            __syncwarp();
        } else {
            // tail fallback (unused when E % 32 == 0)
#pragma unroll
            for (int nt2 = 0; nt2 < 8; ++nt2) {
                const int col = nt2 * 8 + 2 * tig;
                const float bx = b2s[col], by = b2s[col + 1];
#pragma unroll
                for (int m = 0; m < 2; ++m) {
                    const float* cp = C2 + (nt2 * 2 + m) * 4;
                    if (ebase + 16 * m < E) {
                        float2 o; o.x = cp[0] + bx; o.y = cp[1] + by;
                        *(float2*)(out + eo[2 * m] + col) = o;
                    }
                    if (ebase + 16 * m + 8 < E) {
                        float2 o; o.x = cp[2] + bx; o.y = cp[3] + by;
                        *(float2*)(out + eo[2 * m + 1] + col) = o;
                    }
                }
            }
        }
    }
}

extern "C" void kernel_launch(void* const* d_in, const int* in_sizes, int n_in,
                              void* d_out, int out_size) {
    const float* src   = (const float*)d_in[0];
    const float* dest  = (const float*)d_in[1];
    /* d_in[2] = edge_attr, unused by the reference */
    const float* u     = (const float*)d_in[3];
    const int*   batch = (const int*)d_in[4];
    const float* W1    = (const float*)d_in[5];
    const float* b1    = (const float*)d_in[6];
    const float* W2    = (const float*)d_in[7];
    const float* b2    = (const float*)d_in[8];
    float* out = (float*)d_out;

    int E = in_sizes[4];
    int B = in_sizes[3] / FXD;

    ubb_kernel<<<B, 256>>>(u, W1, b1);

    int nsm = 148;
    cudaDeviceGetAttribute(&nsm, cudaDevAttrMultiProcessorCount, 0);
    long ngroups = ((long)E + 31) >> 5;
    long maxcta  = (ngroups + NW - 1) / NW;
    int grid = (int)(maxcta < (long)nsm ? maxcta : (long)nsm);

    cudaFuncSetAttribute(edge_mlp_hmma,
                         cudaFuncAttributeMaxDynamicSharedMemorySize, SMEM_SZ);
    edge_mlp_hmma<<<grid, NTHR, SMEM_SZ>>>(src, dest, batch, W1, W2, b2, out, E, B);
}

// round 15
// speedup vs baseline: 1.0412x; 1.0002x over previous
#include <cuda_runtime.h>
#include <cuda_fp16.h>
#include <stdint.h>

#define FXD 64
#define HD 256
#define NTHR 256
#define NW   8

// ---- Precomputed u[b]@W1[128:192] + b1 : [512,128] half2 ----
__device__ __align__(16) __half2 g_ubbh[512 * 128];

__global__ void ubb_kernel(const float* __restrict__ u,
                           const float* __restrict__ W1,
                           const float* __restrict__ b1) {
    __shared__ float us[FXD];
    __shared__ float accs[HD];
    int b = blockIdx.x, c = threadIdx.x;
    if (c < FXD) us[c] = u[b * FXD + c];
    __syncthreads();
    float acc = b1[c];
#pragma unroll 16
    for (int k = 0; k < FXD; ++k)
        acc = fmaf(us[k], W1[(2 * FXD + k) * HD + c], acc);
    accs[c] = acc;
    __syncthreads();
    if (c < 128)
        g_ubbh[b * 128 + c] = __floats2half2_rn(accs[2 * c], accs[2 * c + 1]);
}

__device__ __forceinline__ uint32_t packf16(float a, float b) {
    __half2 h = __floats2half2_rn(a, b);
    return *reinterpret_cast<uint32_t*>(&h);
}

__device__ __forceinline__ void mma16816(float* c, const uint32_t* a,
                                         uint32_t b0, uint32_t b1) {
    asm volatile(
        "mma.sync.aligned.m16n8k16.row.col.f32.f16.f16.f32 "
        "{%0,%1,%2,%3}, {%4,%5,%6,%7}, {%8,%9}, {%0,%1,%2,%3};"
        : "+f"(c[0]), "+f"(c[1]), "+f"(c[2]), "+f"(c[3])
        : "r"(a[0]), "r"(a[1]), "r"(a[2]), "r"(a[3]), "r"(b0), "r"(b1));
}

// SMEM (uint4 units):
//   w1s 4096 (64KB), w2s 2048 (32KB), outbuf 8 warps x 32x68 floats (68KB), b2 64 floats
#define W2_OFF   4096
#define OUT_OFF  6144
#define B2_OFF   (6144 + 4352)
#define SMEM_SZ  ((6144 + 4352 + 16) * 16)
#define OSTRIDE  68

__global__ __launch_bounds__(NTHR, 1)
void edge_mlp_hmma(const float* __restrict__ src,
                   const float* __restrict__ dst,
                   const int* __restrict__ batch,
                   const float* __restrict__ W1,
                   const float* __restrict__ W2,
                   const float* __restrict__ b2,
                   float* __restrict__ out, int E, int B)
{
    extern __shared__ uint4 smem4[];
    uint4* w1s = smem4;
    uint4* w2s = smem4 + W2_OFF;
    float* b2s = (float*)(smem4 + B2_OFF);

    const int tid  = threadIdx.x;
    const int wid  = tid >> 5;
    const int lane = tid & 31;
    const int gg   = lane >> 2;   // group row
    const int tig  = lane & 3;    // thread in group

    float* outs = (float*)(smem4 + OUT_OFF) + wid * (32 * OSTRIDE);

    // ---- stage W1 fp16 B-fragments ----
    for (int i = tid; i < 8 * 16 * 32 * 4; i += NTHR) {
        int c = i & 3, t = (i >> 2) & 31, ntp = (i >> 7) & 15, s = i >> 11;
        int h = c >> 1, p = c & 1;
        int n  = (2 * ntp + h) * 8 + (t >> 2);
        int k0 = s * 16 + 2 * (t & 3) + p * 8;
        ((uint32_t*)&w1s[(s * 16 + ntp) * 32 + t])[c] =
            packf16(W1[k0 * HD + n], W1[(k0 + 1) * HD + n]);
    }
    // ---- stage W2 ----
    for (int i = tid; i < 16 * 4 * 32 * 4; i += NTHR) {
        int c = i & 3, t = (i >> 2) & 31, ntp = (i >> 7) & 3, s = i >> 9;
        int h = c >> 1, p = c & 1;
        int n  = (2 * ntp + h) * 8 + (t >> 2);
        int k0 = s * 16 + 2 * (t & 3) + p * 8;
        ((uint32_t*)&w2s[(s * 4 + ntp) * 32 + t])[c] =
            packf16(W2[k0 * 64 + n], W2[(k0 + 1) * 64 + n]);
    }
    if (tid < 64) b2s[tid] = b2[tid];
    __syncthreads();

    // ---- phase-offset: second warp on each SMSP starts ~half a chunk later ----
    if (wid >= 4) {
        unsigned long long t0 = clock64();
        while (clock64() - t0 < 700ull) { }
    }

    // ---- warp-autonomous loop over 32-edge groups ----
    const int ngroups = (E + 31) >> 5;
    const int gw0     = blockIdx.x * NW + wid;
    const int gstride = gridDim.x * NW;

    for (int g = gw0; g < ngroups; g += gstride) {
        const int ebase = g * 32 + gg;
        uint32_t eo[4];   // x row offsets (floats)
        uint32_t uo[4];   // ubbh row offsets (half2)
#pragma unroll
        for (int j = 0; j < 4; ++j) {
            int e = ebase + 8 * j;
            int ec = e < E ? e : (E - 1);
            eo[j] = (uint32_t)ec * 64u;
            int bi = batch[ec];
            bi = min(max(bi, 0), B - 1);
            uo[j] = (uint32_t)bi * 128u;
        }

        // ---- load A1 fragments: Ah[s][0..3] = mtile0, [4..7] = mtile1 ----
        uint32_t Ah[8][8];
#pragma unroll
        for (int s = 0; s < 8; ++s) {
            const float* xp = (s < 4) ? dst : src;
            const int k = (s & 3) * 16 + 2 * tig;
#pragma unroll
            for (int m = 0; m < 2; ++m) {
                float2 pa0 = *(const float2*)(xp + eo[2 * m]     + k);
                float2 pa1 = *(const float2*)(xp + eo[2 * m]     + k + 8);
                float2 pb0 = *(const float2*)(xp + eo[2 * m + 1] + k);
                float2 pb1 = *(const float2*)(xp + eo[2 * m + 1] + k + 8);
                Ah[s][4 * m + 0] = packf16(pa0.x, pa0.y);
                Ah[s][4 * m + 1] = packf16(pb0.x, pb0.y);
                Ah[s][4 * m + 2] = packf16(pa1.x, pa1.y);
                Ah[s][4 * m + 3] = packf16(pb1.x, pb1.y);
            }
        }

        // C2[(nt2*2 + m)*4 + r] : 32 rows x 64 cols
        float C2[64];
#pragma unroll
        for (int i = 0; i < 64; ++i) C2[i] = 0.f;

        // ---- software-pipelined chunk loop ----
        // iteration c1: GEMM1(c1), GEMM2(c1-1), epi(c1)->A2, prefetch U(c1+1)/wv2(c1)
        uint32_t A2[2][4];
        __half2 U[2][2][2];
        uint4 wv2[4];

        // prolog: U for chunk 0
#pragma unroll
        for (int m = 0; m < 2; ++m)
#pragma unroll
            for (int h = 0; h < 2; ++h) {
                const int ci = h * 4 + tig;
                U[m][h][0] = g_ubbh[uo[2 * m]     + ci];
                U[m][h][1] = g_ubbh[uo[2 * m + 1] + ci];
            }

        float C1[16];
#pragma unroll
        for (int c1 = 0; c1 <= 16; ++c1) {
            // (1) GEMM1 chunk c1 (skipped on epilogue-only tail iteration)
            if (c1 < 16) {
#pragma unroll
                for (int i = 0; i < 16; ++i) C1[i] = 0.f;
                uint4 wv = w1s[(0 * 16 + c1) * 32 + lane];
#pragma unroll
                for (int s = 0; s < 8; ++s) {
                    uint4 wvn;
                    if (s < 7) wvn = w1s[((s + 1) * 16 + c1) * 32 + lane];
#pragma unroll
                    for (int m = 0; m < 2; ++m) {
                        mma16816(C1 + (0 * 2 + m) * 4, Ah[s] + 4 * m, wv.x, wv.y);
                        mma16816(C1 + (1 * 2 + m) * 4, Ah[s] + 4 * m, wv.z, wv.w);
                    }
                    wv = wvn;
                }
            }

            // (2) GEMM2 for chunk c1-1 (A2 + wv2 produced last iteration)
            if (c1 >= 1) {
#pragma unroll
                for (int ntp = 0; ntp < 4; ++ntp) {
#pragma unroll
                    for (int m = 0; m < 2; ++m) {
                        mma16816(C2 + ((2 * ntp + 0) * 2 + m) * 4, A2[m], wv2[ntp].x, wv2[ntp].y);
                        mma16816(C2 + ((2 * ntp + 1) * 2 + m) * 4, A2[m], wv2[ntp].z, wv2[ntp].w);
                    }
                }
            }

            if (c1 < 16) {
                // (3) epilogue: A2 = relu(f16(C1) + U)   (consumes U, frees it)
                const __half2 hz = __floats2half2_rn(0.f, 0.f);
#pragma unroll
                for (int m = 0; m < 2; ++m) {
#pragma unroll
                    for (int h = 0; h < 2; ++h) {
                        const float* cp = C1 + (h * 2 + m) * 4;
                        __half2 t0 = __hmax2(__hadd2(__floats2half2_rn(cp[0], cp[1]), U[m][h][0]), hz);
                        __half2 t1 = __hmax2(__hadd2(__floats2half2_rn(cp[2], cp[3]), U[m][h][1]), hz);
                        A2[m][2 * h + 0] = *reinterpret_cast<uint32_t*>(&t0);
                        A2[m][2 * h + 1] = *reinterpret_cast<uint32_t*>(&t1);
                    }
                }

                // (4) prefetch U for chunk c1+1 into the same registers
                if (c1 < 15) {
#pragma unroll
                    for (int m = 0; m < 2; ++m)
#pragma unroll
                        for (int h = 0; h < 2; ++h) {
                            const int ci = (c1 + 1) * 8 + h * 4 + tig;
                            U[m][h][0] = g_ubbh[uo[2 * m]     + ci];
                            U[m][h][1] = g_ubbh[uo[2 * m + 1] + ci];
                        }
                }

                // (5) prefetch wv2 for chunk c1's GEMM2 (used next iteration)
#pragma unroll
                for (int ntp = 0; ntp < 4; ++ntp)
                    wv2[ntp] = w2s[(c1 * 4 + ntp) * 32 + lane];
            }
        }

        // ---- store: stage C2 in smem, then coalesced STG.128 ----
        if (g * 32 + 32 <= E) {
            __syncwarp();
#pragma unroll
            for (int nt2 = 0; nt2 < 8; ++nt2) {
                const int col = nt2 * 8 + 2 * tig;
#pragma unroll
                for (int m = 0; m < 2; ++m) {
                    const float* cp = C2 + (nt2 * 2 + m) * 4;
                    const int r0 = 16 * m + gg;
                    *(float2*)(outs + r0 * OSTRIDE + col)       = make_float2(cp[0], cp[1]);
                    *(float2*)(outs + (r0 + 8) * OSTRIDE + col) = make_float2(cp[2], cp[3]);
                }
            }
            __syncwarp();
            float* og = out + (uint32_t)g * 2048u;
            const float4* b2v = (const float4*)b2s;
#pragma unroll
            for (int t = 0; t < 16; ++t) {
                int idx = t * 32 + lane;
                int r = idx >> 4, c4 = idx & 15;
                float4 v = *(const float4*)(outs + r * OSTRIDE + c4 * 4);
                float4 bb = b2v[c4];
                v.x += bb.x; v.y += bb.y; v.z += bb.z; v.w += bb.w;
                *(float4*)(og + idx * 4) = v;
            }
            __syncwarp();
        } else {
            // tail fallback (unused when E % 32 == 0)
#pragma unroll
            for (int nt2 = 0; nt2 < 8; ++nt2) {
                const int col = nt2 * 8 + 2 * tig;
                const float bx = b2s[col], by = b2s[col + 1];
#pragma unroll
                for (int m = 0; m < 2; ++m) {
                    const float* cp = C2 + (nt2 * 2 + m) * 4;
                    if (ebase + 16 * m < E) {
                        float2 o; o.x = cp[0] + bx; o.y = cp[1] + by;
                        *(float2*)(out + eo[2 * m] + col) = o;
                    }
                    if (ebase + 16 * m + 8 < E) {
                        float2 o; o.x = cp[2] + bx; o.y = cp[3] + by;
                        *(float2*)(out + eo[2 * m + 1] + col) = o;
                    }
                }
            }
        }
    }
}

extern "C" void kernel_launch(void* const* d_in, const int* in_sizes, int n_in,
                              void* d_out, int out_size) {
    const float* src   = (const float*)d_in[0];
    const float* dest  = (const float*)d_in[1];
    /* d_in[2] = edge_attr, unused by the reference */
    const float* u     = (const float*)d_in[3];
    const int*   batch = (const int*)d_in[4];
    const float* W1    = (const float*)d_in[5];
    const float* b1    = (const float*)d_in[6];
    const float* W2    = (const float*)d_in[7];
    const float* b2    = (const float*)d_in[8];
    float* out = (float*)d_out;

    int E = in_sizes[4];
    int B = in_sizes[3] / FXD;

    ubb_kernel<<<B, 256>>>(u, W1, b1);

    int nsm = 148;
    cudaDeviceGetAttribute(&nsm, cudaDevAttrMultiProcessorCount, 0);
    long ngroups = ((long)E + 31) >> 5;
    long maxcta  = (ngroups + NW - 1) / NW;
    int grid = (int)(maxcta < (long)nsm ? maxcta : (long)nsm);

    cudaFuncSetAttribute(edge_mlp_hmma,
                         cudaFuncAttributeMaxDynamicSharedMemorySize, SMEM_SZ);
    edge_mlp_hmma<<<grid, NTHR, SMEM_SZ>>>(src, dest, batch, W1, W2, b2, out, E, B);
}

// round 16
// speedup vs baseline: 1.1255x; 1.0810x over previous
#include <cuda_runtime.h>
#include <cuda_fp16.h>
#include <stdint.h>

#define FXD 64
#define HD 256
#define NTHR 256
#define NW   8

// ---- Precomputed u[b]@W1[128:192] + b1, stored PERMUTED as half2:
//      pos p = cpair*16 + t*4 + parity*2 + h  holds logical cols
//      L, L+1 with L = (2*cpair+parity)*16 + 4*t + 2*h
__device__ __align__(16) __half2 g_ubbh[512 * 128];

__global__ void ubb_kernel(const float* __restrict__ u,
                           const float* __restrict__ W1,
                           const float* __restrict__ b1) {
    __shared__ float us[FXD];
    __shared__ float accs[HD];
    int b = blockIdx.x, c = threadIdx.x;
    if (c < FXD) us[c] = u[b * FXD + c];
    __syncthreads();
    float acc = b1[c];
#pragma unroll 16
    for (int k = 0; k < FXD; ++k)
        acc = fmaf(us[k], W1[(2 * FXD + k) * HD + c], acc);
    accs[c] = acc;
    __syncthreads();
    if (c < 128) {
        int cpair  = c >> 4;
        int t      = (c >> 2) & 3;
        int parity = (c >> 1) & 1;
        int h      = c & 1;
        int L = (2 * cpair + parity) * 16 + 4 * t + 2 * h;
        g_ubbh[b * 128 + c] = __floats2half2_rn(accs[L], accs[L + 1]);
    }
}

__device__ __forceinline__ uint32_t packf16(float a, float b) {
    __half2 h = __floats2half2_rn(a, b);
    return *reinterpret_cast<uint32_t*>(&h);
}

__device__ __forceinline__ void mma16816(float* c, const uint32_t* a,
                                         uint32_t b0, uint32_t b1) {
    asm volatile(
        "mma.sync.aligned.m16n8k16.row.col.f32.f16.f16.f32 "
        "{%0,%1,%2,%3}, {%4,%5,%6,%7}, {%8,%9}, {%0,%1,%2,%3};"
        : "+f"(c[0]), "+f"(c[1]), "+f"(c[2]), "+f"(c[3])
        : "r"(a[0]), "r"(a[1]), "r"(a[2]), "r"(a[3]), "r"(b0), "r"(b1));
}

// SMEM (uint4 units):
//   w1s 4096 (64KB), w2s 2048 (32KB), outbuf 8 warps x 32x68 floats (68KB), b2 64 floats
#define W2_OFF   4096
#define OUT_OFF  6144
#define B2_OFF   (6144 + 4352)
#define SMEM_SZ  ((6144 + 4352 + 16) * 16)
#define OSTRIDE  68

__global__ __launch_bounds__(NTHR, 1)
void edge_mlp_hmma(const float* __restrict__ src,
                   const float* __restrict__ dst,
                   const int* __restrict__ batch,
                   const float* __restrict__ W1,
                   const float* __restrict__ W2,
                   const float* __restrict__ b2,
                   float* __restrict__ out, int E, int B)
{
    extern __shared__ uint4 smem4[];
    uint4* w1s = smem4;
    uint4* w2s = smem4 + W2_OFF;
    float* b2s = (float*)(smem4 + B2_OFF);

    const int tid  = threadIdx.x;
    const int wid  = tid >> 5;
    const int lane = tid & 31;
    const int gg   = lane >> 2;   // group row
    const int tig  = lane & 3;    // thread in group

    float* outs = (float*)(smem4 + OUT_OFF) + wid * (32 * OSTRIDE);

    // ---- stage W1 fp16 B-fragments (k-rows PERMUTED: frag k 2q+8p+d -> logical 4q+2p+d) ----
    for (int i = tid; i < 8 * 16 * 32 * 4; i += NTHR) {
        int c = i & 3, t = (i >> 2) & 31, ntp = (i >> 7) & 15, s = i >> 11;
        int h = c >> 1, p = c & 1;
        // n-dim PERMUTED: physical col (h-tile, nphys=t>>2) -> logical 4*(nphys>>1) + 2*h + (nphys&1)
        int nphys = t >> 2;
        int n  = ntp * 16 + 4 * (nphys >> 1) + 2 * h + (nphys & 1);
        int k0 = s * 16 + 4 * (t & 3) + 2 * p;
        ((uint32_t*)&w1s[(s * 16 + ntp) * 32 + t])[c] =
            packf16(W1[k0 * HD + n], W1[(k0 + 1) * HD + n]);
    }
    // ---- stage W2 (k-rows permuted to match A2 logical layout; n unpermuted) ----
    for (int i = tid; i < 16 * 4 * 32 * 4; i += NTHR) {
        int c = i & 3, t = (i >> 2) & 31, ntp = (i >> 7) & 3, s = i >> 9;
        int h = c >> 1, p = c & 1;
        int n  = (2 * ntp + h) * 8 + (t >> 2);
        int k0 = s * 16 + 4 * (t & 3) + 2 * p;
        ((uint32_t*)&w2s[(s * 4 + ntp) * 32 + t])[c] =
            packf16(W2[k0 * 64 + n], W2[(k0 + 1) * 64 + n]);
    }
    if (tid < 64) b2s[tid] = b2[tid];
    __syncthreads();

    // ---- phase-offset: second warp on each SMSP starts ~half a chunk later ----
    if (wid >= 4) {
        unsigned long long t0 = clock64();
        while (clock64() - t0 < 700ull) { }
    }

    // ---- warp-autonomous loop over 32-edge groups ----
    const int ngroups = (E + 31) >> 5;
    const int gw0     = blockIdx.x * NW + wid;
    const int gstride = gridDim.x * NW;

    const uint4* ubb4 = (const uint4*)g_ubbh;

    for (int g = gw0; g < ngroups; g += gstride) {
        const int ebase = g * 32 + gg;
        uint32_t eo[4];   // x row offsets (floats)
        uint32_t uo4[4];  // ubb row offsets (uint4 units)
#pragma unroll
        for (int j = 0; j < 4; ++j) {
            int e = ebase + 8 * j;
            int ec = e < E ? e : (E - 1);
            eo[j] = (uint32_t)ec * 64u;
            int bi = batch[ec];
            bi = min(max(bi, 0), B - 1);
            uo4[j] = (uint32_t)bi * 32u;
        }

        // ---- load A1 fragments via float4 (k-cols permuted: slots <- cols 4*tig..4*tig+3) ----
        uint32_t Ah[8][8];
#pragma unroll
        for (int s = 0; s < 8; ++s) {
            const float* xp = (s < 4) ? dst : src;
            const int kb = (s & 3) * 16 + 4 * tig;
#pragma unroll
            for (int m = 0; m < 2; ++m) {
                float4 fv = *(const float4*)(xp + eo[2 * m]     + kb);
                float4 gv = *(const float4*)(xp + eo[2 * m + 1] + kb);
                Ah[s][4 * m + 0] = packf16(fv.x, fv.y);
                Ah[s][4 * m + 1] = packf16(gv.x, gv.y);
                Ah[s][4 * m + 2] = packf16(fv.z, fv.w);
                Ah[s][4 * m + 3] = packf16(gv.z, gv.w);
            }
        }

        // C2[(nt2*2 + m)*4 + r] : 32 rows x 64 cols
        float C2[64];
#pragma unroll
        for (int i = 0; i < 64; ++i) C2[i] = 0.f;

        // ---- 8 chunk-pairs; one uint4 ubb load per (row j, pair) ----
#pragma unroll
        for (int cp = 0; cp < 8; ++cp) {
            uint4 Uq[4];
#pragma unroll
            for (int j = 0; j < 4; ++j)
                Uq[j] = ubb4[uo4[j] + cp * 4 + tig];

#pragma unroll
            for (int q = 0; q < 2; ++q) {
                const int c1 = 2 * cp + q;

                // GEMM1 chunk with double-buffered weight fragments
                float C1[16];
#pragma unroll
                for (int i = 0; i < 16; ++i) C1[i] = 0.f;
                uint4 wv = w1s[(0 * 16 + c1) * 32 + lane];
#pragma unroll
                for (int s = 0; s < 8; ++s) {
                    uint4 wvn;
                    if (s < 7) wvn = w1s[((s + 1) * 16 + c1) * 32 + lane];
#pragma unroll
                    for (int m = 0; m < 2; ++m) {
                        mma16816(C1 + (0 * 2 + m) * 4, Ah[s] + 4 * m, wv.x, wv.y);
                        mma16816(C1 + (1 * 2 + m) * 4, Ah[s] + 4 * m, wv.z, wv.w);
                    }
                    wv = wvn;
                }

                // preload GEMM2 fragments
                uint4 wv2[4];
#pragma unroll
                for (int ntp = 0; ntp < 4; ++ntp)
                    wv2[ntp] = w2s[(c1 * 4 + ntp) * 32 + lane];

                // epilogue in half2: A2 = relu(f16(C1) + ubbh)
                uint32_t A2[2][4];
                const __half2 hz = __floats2half2_rn(0.f, 0.f);
#pragma unroll
                for (int m = 0; m < 2; ++m) {
#pragma unroll
                    for (int h = 0; h < 2; ++h) {
                        const float* cpp = C1 + (h * 2 + m) * 4;
                        __half2 u0 = ((const __half2*)&Uq[2 * m + 0])[q * 2 + h];
                        __half2 u1 = ((const __half2*)&Uq[2 * m + 1])[q * 2 + h];
                        __half2 t0 = __hmax2(__hadd2(__floats2half2_rn(cpp[0], cpp[1]), u0), hz);
                        __half2 t1 = __hmax2(__hadd2(__floats2half2_rn(cpp[2], cpp[3]), u1), hz);
                        A2[m][2 * h + 0] = *reinterpret_cast<uint32_t*>(&t0);
                        A2[m][2 * h + 1] = *reinterpret_cast<uint32_t*>(&t1);
                    }
                }

                // GEMM2 partial: k-step c1
#pragma unroll
                for (int ntp = 0; ntp < 4; ++ntp) {
#pragma unroll
                    for (int m = 0; m < 2; ++m) {
                        mma16816(C2 + ((2 * ntp + 0) * 2 + m) * 4, A2[m], wv2[ntp].x, wv2[ntp].y);
                        mma16816(C2 + ((2 * ntp + 1) * 2 + m) * 4, A2[m], wv2[ntp].z, wv2[ntp].w);
                    }
                }
            }
        }

        // ---- store: stage C2 in smem, then coalesced STG.128 ----
        if (g * 32 + 32 <= E) {
            __syncwarp();
#pragma unroll
            for (int nt2 = 0; nt2 < 8; ++nt2) {
                const int col = nt2 * 8 + 2 * tig;
#pragma unroll
                for (int m = 0; m < 2; ++m) {
                    const float* cpo = C2 + (nt2 * 2 + m) * 4;
                    const int r0 = 16 * m + gg;
                    *(float2*)(outs + r0 * OSTRIDE + col)       = make_float2(cpo[0], cpo[1]);
                    *(float2*)(outs + (r0 + 8) * OSTRIDE + col) = make_float2(cpo[2], cpo[3]);
                }
            }
            __syncwarp();
            float* og = out + (uint32_t)g * 2048u;
            const float4* b2v = (const float4*)b2s;
#pragma unroll
            for (int t = 0; t < 16; ++t) {
                int idx = t * 32 + lane;
                int r = idx >> 4, c4 = idx & 15;
                float4 v = *(const float4*)(outs + r * OSTRIDE + c4 * 4);
                float4 bb = b2v[c4];
                v.x += bb.x; v.y += bb.y; v.z += bb.z; v.w += bb.w;
                *(float4*)(og + idx * 4) = v;
            }
            __syncwarp();
        } else {
            // tail fallback (unused when E % 32 == 0)
#pragma unroll
            for (int nt2 = 0; nt2 < 8; ++nt2) {
                const int col = nt2 * 8 + 2 * tig;
                const float bx = b2s[col], by = b2s[col + 1];
#pragma unroll
                for (int m = 0; m < 2; ++m) {
                    const float* cpo = C2 + (nt2 * 2 + m) * 4;
                    if (ebase + 16 * m < E) {
                        float2 o; o.x = cpo[0] + bx; o.y = cpo[1] + by;
                        *(float2*)(out + eo[2 * m] + col) = o;
                    }
                    if (ebase + 16 * m + 8 < E) {
                        float2 o; o.x = cpo[2] + bx; o.y = cpo[3] + by;
                        *(float2*)(out + eo[2 * m + 1] + col) = o;
                    }
                }
            }
        }
    }
}

extern "C" void kernel_launch(void* const* d_in, const int* in_sizes, int n_in,
                              void* d_out, int out_size) {
    const float* src   = (const float*)d_in[0];
    const float* dest  = (const float*)d_in[1];
    /* d_in[2] = edge_attr, unused by the reference */
    const float* u     = (const float*)d_in[3];
    const int*   batch = (const int*)d_in[4];
    const float* W1    = (const float*)d_in[5];
    const float* b1    = (const float*)d_in[6];
    const float* W2    = (const float*)d_in[7];
    const float* b2    = (const float*)d_in[8];
    float* out = (float*)d_out;

    int E = in_sizes[4];
    int B = in_sizes[3] / FXD;

    ubb_kernel<<<B, 256>>>(u, W1, b1);

    int nsm = 148;
    cudaDeviceGetAttribute(&nsm, cudaDevAttrMultiProcessorCount, 0);
    long ngroups = ((long)E + 31) >> 5;
    long maxcta  = (ngroups + NW - 1) / NW;
    int grid = (int)(maxcta < (long)nsm ? maxcta : (long)nsm);

    cudaFuncSetAttribute(edge_mlp_hmma,
                         cudaFuncAttributeMaxDynamicSharedMemorySize, SMEM_SZ);
    edge_mlp_hmma<<<grid, NTHR, SMEM_SZ>>>(src, dest, batch, W1, W2, b2, out, E, B);
}

// round 17
// speedup vs baseline: 1.1997x; 1.0659x over previous
#include <cuda_runtime.h>
#include <cuda_fp16.h>
#include <stdint.h>

#define FXD 64
#define HD 256
#define NTHR 256
#define NW   8

// ---- Precomputed u[b]@W1[128:192] + b1, stored PERMUTED as half2:
//      pos p = cpair*16 + t*4 + parity*2 + h  holds logical cols
//      L, L+1 with L = (2*cpair+parity)*16 + 4*t + 2*h
__device__ __align__(16) __half2 g_ubbh[512 * 128];

__global__ void ubb_kernel(const float* __restrict__ u,
                           const float* __restrict__ W1,
                           const float* __restrict__ b1) {
    __shared__ float us[FXD];
    __shared__ float accs[HD];
    int b = blockIdx.x, c = threadIdx.x;
    if (c < FXD) us[c] = u[b * FXD + c];
    __syncthreads();
    float acc = b1[c];
#pragma unroll 16
    for (int k = 0; k < FXD; ++k)
        acc = fmaf(us[k], W1[(2 * FXD + k) * HD + c], acc);
    accs[c] = acc;
    __syncthreads();
    if (c < 128) {
        int cpair  = c >> 4;
        int t      = (c >> 2) & 3;
        int parity = (c >> 1) & 1;
        int h      = c & 1;
        int L = (2 * cpair + parity) * 16 + 4 * t + 2 * h;
        g_ubbh[b * 128 + c] = __floats2half2_rn(accs[L], accs[L + 1]);
    }
}

__device__ __forceinline__ uint32_t packf16(float a, float b) {
    __half2 h = __floats2half2_rn(a, b);
    return *reinterpret_cast<uint32_t*>(&h);
}

// fp32-accum MMA (GEMM2)
__device__ __forceinline__ void mma16816(float* c, const uint32_t* a,
                                         uint32_t b0, uint32_t b1) {
    asm volatile(
        "mma.sync.aligned.m16n8k16.row.col.f32.f16.f16.f32 "
        "{%0,%1,%2,%3}, {%4,%5,%6,%7}, {%8,%9}, {%0,%1,%2,%3};"
        : "+f"(c[0]), "+f"(c[1]), "+f"(c[2]), "+f"(c[3])
        : "r"(a[0]), "r"(a[1]), "r"(a[2]), "r"(a[3]), "r"(b0), "r"(b1));
}

// fp16-accum MMA (GEMM1): D packs {row gg cols(2t,2t+1)} , {row gg+8 cols(2t,2t+1)}
__device__ __forceinline__ void mma16816h(uint32_t* c, const uint32_t* a,
                                          uint32_t b0, uint32_t b1) {
    asm volatile(
        "mma.sync.aligned.m16n8k16.row.col.f16.f16.f16.f16 "
        "{%0,%1}, {%2,%3,%4,%5}, {%6,%7}, {%0,%1};"
        : "+r"(c[0]), "+r"(c[1])
        : "r"(a[0]), "r"(a[1]), "r"(a[2]), "r"(a[3]), "r"(b0), "r"(b1));
}

// SMEM (uint4 units):
//   w1s 4096 (64KB), w2s 2048 (32KB), outbuf 8 warps x 32x68 floats (68KB), b2 64 floats
#define W2_OFF   4096
#define OUT_OFF  6144
#define B2_OFF   (6144 + 4352)
#define SMEM_SZ  ((6144 + 4352 + 16) * 16)
#define OSTRIDE  68

__global__ __launch_bounds__(NTHR, 1)
void edge_mlp_hmma(const float* __restrict__ src,
                   const float* __restrict__ dst,
                   const int* __restrict__ batch,
                   const float* __restrict__ W1,
                   const float* __restrict__ W2,
                   const float* __restrict__ b2,
                   float* __restrict__ out, int E, int B)
{
    extern __shared__ uint4 smem4[];
    uint4* w1s = smem4;
    uint4* w2s = smem4 + W2_OFF;
    float* b2s = (float*)(smem4 + B2_OFF);

    const int tid  = threadIdx.x;
    const int wid  = tid >> 5;
    const int lane = tid & 31;
    const int gg   = lane >> 2;   // group row
    const int tig  = lane & 3;    // thread in group

    float* outs = (float*)(smem4 + OUT_OFF) + wid * (32 * OSTRIDE);

    // ---- stage W1 fp16 B-fragments (k-rows PERMUTED: frag k 2q+8p+d -> logical 4q+2p+d) ----
    for (int i = tid; i < 8 * 16 * 32 * 4; i += NTHR) {
        int c = i & 3, t = (i >> 2) & 31, ntp = (i >> 7) & 15, s = i >> 11;
        int h = c >> 1, p = c & 1;
        int nphys = t >> 2;
        int n  = ntp * 16 + 4 * (nphys >> 1) + 2 * h + (nphys & 1);
        int k0 = s * 16 + 4 * (t & 3) + 2 * p;
        ((uint32_t*)&w1s[(s * 16 + ntp) * 32 + t])[c] =
            packf16(W1[k0 * HD + n], W1[(k0 + 1) * HD + n]);
    }
    // ---- stage W2 (k-rows permuted to match A2 logical layout; n unpermuted) ----
    for (int i = tid; i < 16 * 4 * 32 * 4; i += NTHR) {
        int c = i & 3, t = (i >> 2) & 31, ntp = (i >> 7) & 3, s = i >> 9;
        int h = c >> 1, p = c & 1;
        int n  = (2 * ntp + h) * 8 + (t >> 2);
        int k0 = s * 16 + 4 * (t & 3) + 2 * p;
        ((uint32_t*)&w2s[(s * 4 + ntp) * 32 + t])[c] =
            packf16(W2[k0 * 64 + n], W2[(k0 + 1) * 64 + n]);
    }
    if (tid < 64) b2s[tid] = b2[tid];
    __syncthreads();

    // ---- phase-offset: second warp on each SMSP starts ~half a chunk later ----
    if (wid >= 4) {
        unsigned long long t0 = clock64();
        while (clock64() - t0 < 700ull) { }
    }

    // ---- warp-autonomous loop over 32-edge groups ----
    const int ngroups = (E + 31) >> 5;
    const int gw0     = blockIdx.x * NW + wid;
    const int gstride = gridDim.x * NW;

    const uint4* ubb4 = (const uint4*)g_ubbh;

    for (int g = gw0; g < ngroups; g += gstride) {
        const int ebase = g * 32 + gg;
        uint32_t eo[4];   // x row offsets (floats)
        uint32_t uo4[4];  // ubb row offsets (uint4 units)
#pragma unroll
        for (int j = 0; j < 4; ++j) {
            int e = ebase + 8 * j;
            int ec = e < E ? e : (E - 1);
            eo[j] = (uint32_t)ec * 64u;
            int bi = batch[ec];
            bi = min(max(bi, 0), B - 1);
            uo4[j] = (uint32_t)bi * 32u;
        }

        // ---- load A1 fragments via float4 (k-cols permuted: slots <- cols 4*tig..4*tig+3) ----
        uint32_t Ah[8][8];
#pragma unroll
        for (int s = 0; s < 8; ++s) {
            const float* xp = (s < 4) ? dst : src;
            const int kb = (s & 3) * 16 + 4 * tig;
#pragma unroll
            for (int m = 0; m < 2; ++m) {
                float4 fv = *(const float4*)(xp + eo[2 * m]     + kb);
                float4 gv = *(const float4*)(xp + eo[2 * m + 1] + kb);
                Ah[s][4 * m + 0] = packf16(fv.x, fv.y);
                Ah[s][4 * m + 1] = packf16(gv.x, gv.y);
                Ah[s][4 * m + 2] = packf16(fv.z, fv.w);
                Ah[s][4 * m + 3] = packf16(gv.z, gv.w);
            }
        }

        // C2[(nt2*2 + m)*4 + r] : 32 rows x 64 cols
        float C2[64];
#pragma unroll
        for (int i = 0; i < 64; ++i) C2[i] = 0.f;

        // ---- 8 chunk-pairs; one uint4 ubb load per (row j, pair) ----
#pragma unroll
        for (int cp = 0; cp < 8; ++cp) {
            uint4 Uq[4];
#pragma unroll
            for (int j = 0; j < 4; ++j)
                Uq[j] = ubb4[uo4[j] + cp * 4 + tig];

#pragma unroll
            for (int q = 0; q < 2; ++q) {
                const int c1 = 2 * cp + q;

                // GEMM1 chunk, fp16 accumulators:
                // C1h[(j*2 + m)*2 + half]: half0 = row gg, half1 = row gg+8
                uint32_t C1h[8];
#pragma unroll
                for (int i = 0; i < 8; ++i) C1h[i] = 0u;
                uint4 wv = w1s[(0 * 16 + c1) * 32 + lane];
#pragma unroll
                for (int s = 0; s < 8; ++s) {
                    uint4 wvn;
                    if (s < 7) wvn = w1s[((s + 1) * 16 + c1) * 32 + lane];
#pragma unroll
                    for (int m = 0; m < 2; ++m) {
                        mma16816h(C1h + (0 * 2 + m) * 2, Ah[s] + 4 * m, wv.x, wv.y);
                        mma16816h(C1h + (1 * 2 + m) * 2, Ah[s] + 4 * m, wv.z, wv.w);
                    }
                    wv = wvn;
                }

                // preload GEMM2 fragments
                uint4 wv2[4];
#pragma unroll
                for (int ntp = 0; ntp < 4; ++ntp)
                    wv2[ntp] = w2s[(c1 * 4 + ntp) * 32 + lane];

                // epilogue in half2: A2 = relu(C1h + ubbh)  (no CVTs)
                uint32_t A2[2][4];
                const __half2 hz = __floats2half2_rn(0.f, 0.f);
#pragma unroll
                for (int m = 0; m < 2; ++m) {
#pragma unroll
                    for (int h = 0; h < 2; ++h) {
                        __half2 d0 = *reinterpret_cast<__half2*>(&C1h[(h * 2 + m) * 2 + 0]);
                        __half2 d1 = *reinterpret_cast<__half2*>(&C1h[(h * 2 + m) * 2 + 1]);
                        __half2 u0 = ((const __half2*)&Uq[2 * m + 0])[q * 2 + h];
                        __half2 u1 = ((const __half2*)&Uq[2 * m + 1])[q * 2 + h];
                        __half2 t0 = __hmax2(__hadd2(d0, u0), hz);
                        __half2 t1 = __hmax2(__hadd2(d1, u1), hz);
                        A2[m][2 * h + 0] = *reinterpret_cast<uint32_t*>(&t0);
                        A2[m][2 * h + 1] = *reinterpret_cast<uint32_t*>(&t1);
                    }
                }

                // GEMM2 partial (fp32 accum): k-step c1
#pragma unroll
                for (int ntp = 0; ntp < 4; ++ntp) {
#pragma unroll
                    for (int m = 0; m < 2; ++m) {
                        mma16816(C2 + ((2 * ntp + 0) * 2 + m) * 4, A2[m], wv2[ntp].x, wv2[ntp].y);
                        mma16816(C2 + ((2 * ntp + 1) * 2 + m) * 4, A2[m], wv2[ntp].z, wv2[ntp].w);
                    }
                }
            }
        }

        // ---- store: stage C2 in smem, then coalesced STG.128 ----
        if (g * 32 + 32 <= E) {
            __syncwarp();
#pragma unroll
            for (int nt2 = 0; nt2 < 8; ++nt2) {
                const int col = nt2 * 8 + 2 * tig;
#pragma unroll
                for (int m = 0; m < 2; ++m) {
                    const float* cpo = C2 + (nt2 * 2 + m) * 4;
                    const int r0 = 16 * m + gg;
                    *(float2*)(outs + r0 * OSTRIDE + col)       = make_float2(cpo[0], cpo[1]);
                    *(float2*)(outs + (r0 + 8) * OSTRIDE + col) = make_float2(cpo[2], cpo[3]);
                }
            }
            __syncwarp();
            float* og = out + (uint32_t)g * 2048u;
            const float4* b2v = (const float4*)b2s;
#pragma unroll
            for (int t = 0; t < 16; ++t) {
                int idx = t * 32 + lane;
                int r = idx >> 4, c4 = idx & 15;
                float4 v = *(const float4*)(outs + r * OSTRIDE + c4 * 4);
                float4 bb = b2v[c4];
                v.x += bb.x; v.y += bb.y; v.z += bb.z; v.w += bb.w;
                *(float4*)(og + idx * 4) = v;
            }
            __syncwarp();
        } else {
            // tail fallback (unused when E % 32 == 0)
#pragma unroll
            for (int nt2 = 0; nt2 < 8; ++nt2) {
                const int col = nt2 * 8 + 2 * tig;
                const float bx = b2s[col], by = b2s[col + 1];
#pragma unroll
                for (int m = 0; m < 2; ++m) {
                    const float* cpo = C2 + (nt2 * 2 + m) * 4;
                    if (ebase + 16 * m < E) {
                        float2 o; o.x = cpo[0] + bx; o.y = cpo[1] + by;
                        *(float2*)(out + eo[2 * m] + col) = o;
                    }
                    if (ebase + 16 * m + 8 < E) {
                        float2 o; o.x = cpo[2] + bx; o.y = cpo[3] + by;
                        *(float2*)(out + eo[2 * m + 1] + col) = o;
                    }
                }
            }
        }
    }
}

extern "C" void kernel_launch(void* const* d_in, const int* in_sizes, int n_in,
                              void* d_out, int out_size) {
    const float* src   = (const float*)d_in[0];
    const float* dest  = (const float*)d_in[1];
    /* d_in[2] = edge_attr, unused by the reference */
    const float* u     = (const float*)d_in[3];
    const int*   batch = (const int*)d_in[4];
    const float* W1    = (const float*)d_in[5];
    const float* b1    = (const float*)d_in[6];
    const float* W2    = (const float*)d_in[7];
    const float* b2    = (const float*)d_in[8];
    float* out = (float*)d_out;

    int E = in_sizes[4];
    int B = in_sizes[3] / FXD;

    ubb_kernel<<<B, 256>>>(u, W1, b1);

    int nsm = 148;
    cudaDeviceGetAttribute(&nsm, cudaDevAttrMultiProcessorCount, 0);
    long ngroups = ((long)E + 31) >> 5;
    long maxcta  = (ngroups + NW - 1) / NW;
    int grid = (int)(maxcta < (long)nsm ? maxcta : (long)nsm);

    cudaFuncSetAttribute(edge_mlp_hmma,
                         cudaFuncAttributeMaxDynamicSharedMemorySize, SMEM_SZ);
    edge_mlp_hmma<<<grid, NTHR, SMEM_SZ>>>(src, dest, batch, W1, W2, b2, out, E, B);
}